// round 13
// baseline (speedup 1.0000x reference)
#include <cuda_runtime.h>
#include <cuda_bf16.h>
#include <cstdint>

// Problem constants (match reference_code)
#define NPTS   1000000
#define NCH    32
#define SDIM   64
#define NKEYS  (SDIM*SDIM*SDIM*SDIM)      // 16,777,216 possible keys (2^24)
#define NWORDS (NKEYS/32)                 // 524,288 bitmap words

// Fused mark+scan config: 128 blocks * 256 threads * 16 words = 524,288
#define SCAN_NBLK 128
#define SCAN_TPB  256
#define WPT       16

// Binning: top 13 bits of 24-bit key -> 8192 bins, ~122 pts/bin,
// ~15KB output window per bin.
#define NBINS      8192
#define BIN_SHIFT  11

// ---- device scratch (static; no allocation allowed) ----
__device__ unsigned int g_bits[NWORDS];      // presence bitmap (2MB)
__device__ unsigned int g_dup[NWORDS];       // "key has >1 point" bitmap (2MB)
__device__ unsigned int g_prefix[NWORDS];    // exclusive popcount prefix per word (2MB)
__device__ int          g_keys[NPTS];        // cached key per point (4MB)
__device__ int          g_order[NPTS];       // bin-sorted point indices (4MB)
__device__ unsigned int g_binCnt[NBINS];     // bin histogram
__device__ unsigned int g_binBase[NBINS];    // bin exclusive offsets (consumed by reorder)
__device__ unsigned int g_desc[SCAN_NBLK];   // decoupled-lookback descriptors
__device__ unsigned int g_total;             // number of unique keys U
__device__ unsigned int g_sync;              // grid-sync counter (reset by k_zero)

// ------------------------------------------------------------------
// K1: zero bitmaps + descriptors + bin counters + sync counter
// grid = 512 x 256 -> 131072 threads, one uint4 per array each
// ------------------------------------------------------------------
__global__ void k_zero() {
    int t = blockIdx.x * blockDim.x + threadIdx.x;   // 131072 threads
    uint4 z = make_uint4(0u, 0u, 0u, 0u);
    reinterpret_cast<uint4*>(g_bits)[t] = z;
    reinterpret_cast<uint4*>(g_dup)[t]  = z;
    if (t < SCAN_NBLK / 4)
        reinterpret_cast<uint4*>(g_desc)[t] = z;
    if (t < NBINS / 4)
        reinterpret_cast<uint4*>(g_binCnt)[t] = z;
    if (t == 0) g_sync = 0;
}

// ------------------------------------------------------------------
// Grid sync for the fused kernel (128 co-resident blocks, wave 1)
// ------------------------------------------------------------------
__device__ __forceinline__ void grid_sync() {
    __syncthreads();
    if (threadIdx.x == 0) {
        __threadfence();
        unsigned v = atomicAdd(&g_sync, 1u) + 1u;
        if (v < (unsigned)SCAN_NBLK) {
            while (atomicAdd(&g_sync, 0u) < (unsigned)SCAN_NBLK)
                __nanosleep(64);
        }
    }
    __syncthreads();
    __threadfence();
}

// ------------------------------------------------------------------
// K2 fused: phase A = mark (keys, presence, dup, bin histogram)
//           grid-sync
//           phase B = decoupled-lookback scan + prefix + dup-row zero
//                     + U capture + (block 0) bin-histogram scan
// ------------------------------------------------------------------
__global__ void __launch_bounds__(SCAN_TPB, 1)
k_markscan(const int4* __restrict__ coords, float4* __restrict__ out4) {
    const unsigned FULL = 0xffffffffu;
    int bid = blockIdx.x, tid = threadIdx.x;
    int lane = tid & 31, wid = tid >> 5;

    // ================= Phase A: mark =================
    {
        int t = bid * SCAN_TPB + tid;                // 0..32767
        for (int i = t; i < NPTS; i += SCAN_NBLK * SCAN_TPB) {
            int4 c = coords[i];
            int key = ((c.x * SDIM + c.y) * SDIM + c.z) * SDIM + c.w;
            g_keys[i] = key;
            unsigned bit = 1u << (key & 31);
            unsigned old = atomicOr(&g_bits[key >> 5], bit);
            if (old & bit) atomicOr(&g_dup[key >> 5], bit);
            atomicAdd(&g_binCnt[(unsigned)key >> BIN_SHIFT], 1u);
        }
    }

    grid_sync();

    // ================= Phase B: scan =================
    int wbase = bid * (SCAN_TPB * WPT) + tid * WPT;

    unsigned w[WPT], dw[WPT], c[WPT];
    #pragma unroll
    for (int j = 0; j < 4; j++) {
        uint4 v = *reinterpret_cast<const uint4*>(&g_bits[wbase + j * 4]);
        w[j*4+0] = v.x; w[j*4+1] = v.y; w[j*4+2] = v.z; w[j*4+3] = v.w;
        uint4 d = *reinterpret_cast<const uint4*>(&g_dup[wbase + j * 4]);
        dw[j*4+0] = d.x; dw[j*4+1] = d.y; dw[j*4+2] = d.z; dw[j*4+3] = d.w;
    }
    unsigned tsum = 0;
    #pragma unroll
    for (int j = 0; j < WPT; j++) { c[j] = __popc(w[j]); tsum += c[j]; }

    unsigned inc = tsum;
    #pragma unroll
    for (int d = 1; d < 32; d <<= 1) {
        unsigned n = __shfl_up_sync(FULL, inc, d);
        if (lane >= d) inc += n;
    }

    __shared__ unsigned ws[8], woff[8];
    __shared__ unsigned sh_agg, sh_excl;
    if (lane == 31) ws[wid] = inc;
    __syncthreads();
    if (tid < 8) {
        unsigned x = ws[tid], s = x;
        #pragma unroll
        for (int d = 1; d < 8; d <<= 1) {
            unsigned n = __shfl_up_sync(0xffu, s, d);
            if (tid >= d) s += n;
        }
        woff[tid] = s - x;
        if (tid == 7) sh_agg = s;
    }
    __syncthreads();
    unsigned agg = sh_agg;

    if (wid == 0) {
        if (bid == 0) {
            if (lane == 0) {
                atomicExch(&g_desc[0], (2u << 30) | agg);
                sh_excl = 0;
            }
        } else {
            if (lane == 0) atomicExch(&g_desc[bid], (1u << 30) | agg);
            unsigned running = 0;
            int base = bid - 1;
            while (true) {
                int idx = base - lane;
                unsigned d = (idx >= 0) ? atomicAdd(&g_desc[idx], 0u)
                                        : (2u << 30);
                unsigned st = d >> 30;
                if (__ballot_sync(FULL, st == 0)) continue;
                unsigned pm  = __ballot_sync(FULL, st == 2);
                unsigned val = d & 0x3fffffffu;
                if (pm) {
                    int p = __ffs(pm) - 1;
                    if (lane > p) val = 0;
                }
                #pragma unroll
                for (int dd = 16; dd > 0; dd >>= 1)
                    val += __shfl_down_sync(FULL, val, dd);
                running += __shfl_sync(FULL, val, 0);
                if (pm) break;
                base -= 32;
            }
            if (lane == 0) {
                atomicExch(&g_desc[bid], (2u << 30) | (running + agg));
                sh_excl = running;
                if (bid == SCAN_NBLK - 1) g_total = running + agg;
            }
        }
    }
    __syncthreads();

    unsigned run = sh_excl + woff[wid] + (inc - tsum);
    unsigned p[WPT];
    #pragma unroll
    for (int j = 0; j < WPT; j++) { p[j] = run; run += c[j]; }
    #pragma unroll
    for (int j = 0; j < 4; j++) {
        uint4 v = make_uint4(p[j*4+0], p[j*4+1], p[j*4+2], p[j*4+3]);
        *reinterpret_cast<uint4*>(&g_prefix[wbase + j * 4]) = v;
    }

    // zero the rows owned by duplicate keys (sparse, ~30K rows)
    float4 z = make_float4(0.f, 0.f, 0.f, 0.f);
    #pragma unroll
    for (int j = 0; j < WPT; j++) {
        unsigned d = dw[j];
        while (d) {
            int b = __ffs(d) - 1;
            d &= d - 1;
            unsigned rank = p[j] + __popc(w[j] & ((1u << b) - 1u));
            float4* row = out4 + (size_t)rank * 8;
            #pragma unroll
            for (int q = 0; q < 8; q++) __stcs(&row[q], z);
        }
    }

    // block 0 (no lookback wait, finishes first): scan bin histogram
    if (bid == 0) {
        __syncthreads();                 // ws/woff reuse
        unsigned bl[NBINS / SCAN_TPB];   // 32 bins per thread
        int b0 = tid * (NBINS / SCAN_TPB);
        unsigned bsum = 0;
        #pragma unroll
        for (int j = 0; j < NBINS / SCAN_TPB; j++) {
            bl[j] = g_binCnt[b0 + j];
            bsum += bl[j];
        }
        unsigned binc = bsum;
        #pragma unroll
        for (int d = 1; d < 32; d <<= 1) {
            unsigned n = __shfl_up_sync(FULL, binc, d);
            if (lane >= d) binc += n;
        }
        if (lane == 31) ws[wid] = binc;
        __syncthreads();
        if (tid < 8) {
            unsigned x = ws[tid], s = x;
            #pragma unroll
            for (int d = 1; d < 8; d <<= 1) {
                unsigned n = __shfl_up_sync(0xffu, s, d);
                if (tid >= d) s += n;
            }
            woff[tid] = s - x;
        }
        __syncthreads();
        unsigned brun = woff[wid] + (binc - bsum);
        #pragma unroll
        for (int j = 0; j < NBINS / SCAN_TPB; j++) {
            g_binBase[b0 + j] = brun;
            brun += bl[j];
        }
    }
}

// ------------------------------------------------------------------
// K3: reorder point indices into key-bin order
// ------------------------------------------------------------------
__global__ void k_reorder() {
    int i = blockIdx.x * blockDim.x + threadIdx.x;
    if (i >= NPTS) return;
    unsigned bin = (unsigned)g_keys[i] >> BIN_SHIFT;
    unsigned pos = atomicAdd(&g_binBase[bin], 1u);
    g_order[pos] = i;
}

// ------------------------------------------------------------------
// K4: scatter features in bin order + zero tail rows [U, N).
// Consecutive rows j belong to the same key bin -> output writes
// cluster inside a ~15KB window (DRAM row-buffer friendly) and the
// metadata words are key-clustered (L2 hits). feats reads are the
// random side now (full 128B line per row, deep read MLP).
// Lane layout: warp covers 8 rows as 4 groups of 8 lanes, ILP=2.
// ------------------------------------------------------------------
__global__ void __launch_bounds__(256)
k_scatter(const float4* __restrict__ feats, float* __restrict__ out) {
    const unsigned FULL = 0xffffffffu;
    int t = blockIdx.x * blockDim.x + threadIdx.x;   // NPTS*4 threads exactly
    int lane = threadIdx.x & 31;
    int g = lane >> 3;                               // group 0..3
    int s = lane & 7;                                // slot 0..7
    int base = (t >> 5) * 8;                         // first order-slot of warp
    int r0 = base + g;                               // order slots handled
    int r1 = base + g + 4;

    unsigned U = g_total;

    // point indices (same address across the 8-lane group -> broadcast)
    int i0 = g_order[r0];
    int i1 = g_order[r1];

    // leader lane resolves metadata for both rows
    unsigned rd0 = 0, rd1 = 0;
    if (s == 0) {
        int k0 = g_keys[i0];
        int k1 = g_keys[i1];
        unsigned wi0 = (unsigned)k0 >> 5, bt0 = (unsigned)k0 & 31;
        unsigned wi1 = (unsigned)k1 >> 5, bt1 = (unsigned)k1 & 31;
        unsigned bw0 = g_bits[wi0];
        unsigned bw1 = g_bits[wi1];
        unsigned rank0 = g_prefix[wi0] + __popc(bw0 & ((1u << bt0) - 1u));
        unsigned rank1 = g_prefix[wi1] + __popc(bw1 & ((1u << bt1) - 1u));
        unsigned dup0 = (g_dup[wi0] >> bt0) & 1u;
        unsigned dup1 = (g_dup[wi1] >> bt1) & 1u;
        rd0 = rank0 | (dup0 << 31);
        rd1 = rank1 | (dup1 << 31);
    }
    rd0 = __shfl_sync(FULL, rd0, lane & ~7);
    rd1 = __shfl_sync(FULL, rd1, lane & ~7);
    unsigned rank0 = rd0 & 0x7fffffffu; bool dup0 = (rd0 >> 31) != 0;
    unsigned rank1 = rd1 & 0x7fffffffu; bool dup1 = (rd1 >> 31) != 0;

    // random full-line feature reads (two independent chains)
    float4 v0 = __ldcs(&feats[(size_t)i0 * 8 + s]);
    float4 v1 = __ldcs(&feats[(size_t)i1 * 8 + s]);

    // tail rows [U, N) -> zero (row index = slot index domain 0..N)
    float4 z = make_float4(0.f, 0.f, 0.f, 0.f);
    if ((unsigned)r0 >= U)
        __stcs(&reinterpret_cast<float4*>(out)[(size_t)r0 * 8 + s], z);
    if ((unsigned)r1 >= U)
        __stcs(&reinterpret_cast<float4*>(out)[(size_t)r1 * 8 + s], z);

    float* dst0 = out + (size_t)rank0 * NCH + s * 4;
    float* dst1 = out + (size_t)rank1 * NCH + s * 4;
    if (!dup0) {
        __stcs(reinterpret_cast<float4*>(dst0), v0);
    } else {
        atomicAdd(dst0 + 0, v0.x);
        atomicAdd(dst0 + 1, v0.y);
        atomicAdd(dst0 + 2, v0.z);
        atomicAdd(dst0 + 3, v0.w);
    }
    if (!dup1) {
        __stcs(reinterpret_cast<float4*>(dst1), v1);
    } else {
        atomicAdd(dst1 + 0, v1.x);
        atomicAdd(dst1 + 1, v1.y);
        atomicAdd(dst1 + 2, v1.z);
        atomicAdd(dst1 + 3, v1.w);
    }
}

// ------------------------------------------------------------------
extern "C" void kernel_launch(void* const* d_in, const int* in_sizes, int n_in,
                              void* d_out, int out_size) {
    const int4*   coords = (const int4*)d_in[0];     // [N,4] int32
    const float4* feats  = (const float4*)d_in[1];   // [N,32] f32 as [N,8] float4
    float*        out    = (float*)d_out;            // [N,32] f32

    (void)in_sizes; (void)n_in; (void)out_size;

    const int TB = 256;

    // K1: reset bitmaps, descriptors, bin counters, sync counter
    k_zero<<<NWORDS / 4 / TB, TB>>>();
    // K2: fused mark + scan (grid-synced persistent kernel, 128 blocks)
    k_markscan<<<SCAN_NBLK, SCAN_TPB>>>(coords, (float4*)d_out);
    // K3: bin-order point reorder
    k_reorder<<<(NPTS + TB - 1) / TB, TB>>>();
    // K4: bin-ordered scatter + tail zero
    k_scatter<<<(NPTS * 4) / TB, TB>>>(feats, out);
}

// round 14
// speedup vs baseline: 1.6549x; 1.6549x over previous
#include <cuda_runtime.h>
#include <cuda_bf16.h>
#include <cstdint>

// Problem constants (match reference_code)
#define NPTS   1000000
#define NCH    32
#define SDIM   64
#define NKEYS  (SDIM*SDIM*SDIM*SDIM)      // 16,777,216 possible keys (2^24)
#define NWORDS (NKEYS/32)                 // 524,288 bitmap words

// Fused scan config: 128 blocks * 256 threads * 16 words = 524,288
#define SCAN_NBLK 128
#define SCAN_TPB  256
#define WPT       16

// ---- device scratch (static; no allocation allowed) ----
__device__ unsigned int g_bits[NWORDS];      // presence bitmap (2MB)
__device__ unsigned int g_dup[NWORDS];       // "key has >1 point" bitmap (2MB)
__device__ uint4        g_meta[NWORDS];      // {bits, prefix, dup, 0} packed (8MB)
__device__ int          g_keys[NPTS];        // cached key per point (4MB)
__device__ unsigned int g_desc[SCAN_NBLK];   // decoupled-lookback descriptors
__device__ unsigned int g_total;             // number of unique keys U

// ------------------------------------------------------------------
// K1: zero bitmaps + lookback descriptors (reset every graph replay)
// ------------------------------------------------------------------
__global__ void k_zero_bits() {
    int t = blockIdx.x * blockDim.x + threadIdx.x;   // NWORDS/4 threads
    uint4 z = make_uint4(0u, 0u, 0u, 0u);
    reinterpret_cast<uint4*>(g_bits)[t] = z;
    reinterpret_cast<uint4*>(g_dup)[t]  = z;
    if (t < SCAN_NBLK / 4)
        reinterpret_cast<uint4*>(g_desc)[t] = z;
}

// ------------------------------------------------------------------
// K2: compute keys, mark presence, detect duplicates (2 pts/thread)
// ------------------------------------------------------------------
__global__ void k_mark(const int4* __restrict__ coords) {
    const int HALF = NPTS / 2;
    int i = blockIdx.x * blockDim.x + threadIdx.x;
    if (i >= HALF) return;
    int4 c0 = coords[i];
    int4 c1 = coords[i + HALF];
    int k0 = ((c0.x * SDIM + c0.y) * SDIM + c0.z) * SDIM + c0.w;
    int k1 = ((c1.x * SDIM + c1.y) * SDIM + c1.z) * SDIM + c1.w;
    g_keys[i]        = k0;
    g_keys[i + HALF] = k1;
    unsigned b0 = 1u << (k0 & 31);
    unsigned b1 = 1u << (k1 & 31);
    unsigned o0 = atomicOr(&g_bits[k0 >> 5], b0);
    unsigned o1 = atomicOr(&g_bits[k1 >> 5], b1);
    if (o0 & b0) atomicOr(&g_dup[k0 >> 5], b0);
    if (o1 & b1) atomicOr(&g_dup[k1 >> 5], b1);
}

// ------------------------------------------------------------------
// K3: fused single-pass scan (decoupled lookback) + packed meta write
//     + dup-row zeroing + U capture.
// ------------------------------------------------------------------
__global__ void __launch_bounds__(SCAN_TPB, 1)
k_scan_fused(float4* __restrict__ out4) {
    const unsigned FULL = 0xffffffffu;
    int bid = blockIdx.x, tid = threadIdx.x;
    int lane = tid & 31, wid = tid >> 5;
    int wbase = bid * (SCAN_TPB * WPT) + tid * WPT;

    unsigned w[WPT], dw[WPT], c[WPT];
    #pragma unroll
    for (int j = 0; j < 4; j++) {
        uint4 v = *reinterpret_cast<const uint4*>(&g_bits[wbase + j * 4]);
        w[j*4+0] = v.x; w[j*4+1] = v.y; w[j*4+2] = v.z; w[j*4+3] = v.w;
        uint4 d = *reinterpret_cast<const uint4*>(&g_dup[wbase + j * 4]);
        dw[j*4+0] = d.x; dw[j*4+1] = d.y; dw[j*4+2] = d.z; dw[j*4+3] = d.w;
    }
    unsigned tsum = 0;
    #pragma unroll
    for (int j = 0; j < WPT; j++) { c[j] = __popc(w[j]); tsum += c[j]; }

    unsigned inc = tsum;
    #pragma unroll
    for (int d = 1; d < 32; d <<= 1) {
        unsigned n = __shfl_up_sync(FULL, inc, d);
        if (lane >= d) inc += n;
    }

    __shared__ unsigned ws[8], woff[8];
    __shared__ unsigned sh_agg, sh_excl;
    if (lane == 31) ws[wid] = inc;
    __syncthreads();
    if (tid < 8) {
        unsigned x = ws[tid], s = x;
        #pragma unroll
        for (int d = 1; d < 8; d <<= 1) {
            unsigned n = __shfl_up_sync(0xffu, s, d);
            if (tid >= d) s += n;
        }
        woff[tid] = s - x;
        if (tid == 7) sh_agg = s;
    }
    __syncthreads();
    unsigned agg = sh_agg;

    if (wid == 0) {
        if (bid == 0) {
            if (lane == 0) {
                atomicExch(&g_desc[0], (2u << 30) | agg);
                sh_excl = 0;
            }
        } else {
            if (lane == 0) atomicExch(&g_desc[bid], (1u << 30) | agg);
            unsigned running = 0;
            int base = bid - 1;
            while (true) {
                int idx = base - lane;
                unsigned d = (idx >= 0) ? atomicAdd(&g_desc[idx], 0u)
                                        : (2u << 30);
                unsigned st = d >> 30;
                if (__ballot_sync(FULL, st == 0)) continue;
                unsigned pm  = __ballot_sync(FULL, st == 2);
                unsigned val = d & 0x3fffffffu;
                if (pm) {
                    int p = __ffs(pm) - 1;
                    if (lane > p) val = 0;
                }
                #pragma unroll
                for (int dd = 16; dd > 0; dd >>= 1)
                    val += __shfl_down_sync(FULL, val, dd);
                running += __shfl_sync(FULL, val, 0);
                if (pm) break;
                base -= 32;
            }
            if (lane == 0) {
                atomicExch(&g_desc[bid], (2u << 30) | (running + agg));
                sh_excl = running;
                if (bid == SCAN_NBLK - 1) g_total = running + agg;
            }
        }
    }
    __syncthreads();

    unsigned run = sh_excl + woff[wid] + (inc - tsum);
    unsigned p[WPT];
    #pragma unroll
    for (int j = 0; j < WPT; j++) { p[j] = run; run += c[j]; }

    // packed metadata: one 16B word per bitmap word -> scatter does a
    // single-sector random load instead of 3 loads to 3 arrays
    #pragma unroll
    for (int j = 0; j < WPT; j++) {
        g_meta[wbase + j] = make_uint4(w[j], p[j], dw[j], 0u);
    }

    // zero the rows owned by duplicate keys (sparse, ~30K rows)
    float4 z = make_float4(0.f, 0.f, 0.f, 0.f);
    #pragma unroll
    for (int j = 0; j < WPT; j++) {
        unsigned d = dw[j];
        while (d) {
            int b = __ffs(d) - 1;
            d &= d - 1;
            unsigned rank = p[j] + __popc(w[j] & ((1u << b) - 1u));
            float4* row = out4 + (size_t)rank * 8;
            #pragma unroll
            for (int q = 0; q < 8; q++) __stcs(&row[q], z);
        }
    }
}

// ------------------------------------------------------------------
// K4: scatter features + zero tail rows [U, N).
// Lane layout: warp covers 8 rows as 4 groups of 8 lanes; thread
// handles slot s of rows (base+g) and (base+g+4) -> ILP=2, and every
// STG.128 writes 4 complete 128B output lines.
// Metadata: leader lane (s==0) does ONE uint4 load per row (packed
// {bits,prefix,dup}) and broadcasts rank|dup via shuffle.
// ------------------------------------------------------------------
__global__ void __launch_bounds__(256)
k_scatter(const float4* __restrict__ feats, float* __restrict__ out) {
    const unsigned FULL = 0xffffffffu;
    int t = blockIdx.x * blockDim.x + threadIdx.x;   // NPTS*4 threads exactly
    int lane = threadIdx.x & 31;
    int g = lane >> 3;                               // group 0..3
    int s = lane & 7;                                // slot 0..7
    int base = (t >> 5) * 8;                         // first row of this warp
    int r0 = base + g;                               // rows handled by thread
    int r1 = base + g + 4;

    unsigned U = g_total;

    // leader lane resolves metadata for both of its group's rows
    unsigned rd0 = 0, rd1 = 0;
    if (s == 0) {
        int k0 = g_keys[r0];
        int k1 = g_keys[r1];
        unsigned wi0 = (unsigned)k0 >> 5, bt0 = (unsigned)k0 & 31;
        unsigned wi1 = (unsigned)k1 >> 5, bt1 = (unsigned)k1 & 31;
        uint4 m0 = g_meta[wi0];
        uint4 m1 = g_meta[wi1];
        unsigned rank0 = m0.y + __popc(m0.x & ((1u << bt0) - 1u));
        unsigned rank1 = m1.y + __popc(m1.x & ((1u << bt1) - 1u));
        unsigned dup0 = (m0.z >> bt0) & 1u;
        unsigned dup1 = (m1.z >> bt1) & 1u;
        rd0 = rank0 | (dup0 << 31);
        rd1 = rank1 | (dup1 << 31);
    }
    rd0 = __shfl_sync(FULL, rd0, lane & ~7);
    rd1 = __shfl_sync(FULL, rd1, lane & ~7);
    unsigned rank0 = rd0 & 0x7fffffffu; bool dup0 = (rd0 >> 31) != 0;
    unsigned rank1 = rd1 & 0x7fffffffu; bool dup1 = (rd1 >> 31) != 0;

    // two independent float4 transfers per thread (streaming reads)
    float4 v0 = __ldcs(&feats[(size_t)r0 * 8 + s]);
    float4 v1 = __ldcs(&feats[(size_t)r1 * 8 + s]);

    // tail rows [U, N) -> zero (disjoint from scatter targets, all < U)
    float4 z = make_float4(0.f, 0.f, 0.f, 0.f);
    if ((unsigned)r0 >= U)
        __stcs(&reinterpret_cast<float4*>(out)[(size_t)r0 * 8 + s], z);
    if ((unsigned)r1 >= U)
        __stcs(&reinterpret_cast<float4*>(out)[(size_t)r1 * 8 + s], z);

    float* dst0 = out + (size_t)rank0 * NCH + s * 4;
    float* dst1 = out + (size_t)rank1 * NCH + s * 4;
    if (!dup0) {
        __stcs(reinterpret_cast<float4*>(dst0), v0);
    } else {
        atomicAdd(dst0 + 0, v0.x);
        atomicAdd(dst0 + 1, v0.y);
        atomicAdd(dst0 + 2, v0.z);
        atomicAdd(dst0 + 3, v0.w);
    }
    if (!dup1) {
        __stcs(reinterpret_cast<float4*>(dst1), v1);
    } else {
        atomicAdd(dst1 + 0, v1.x);
        atomicAdd(dst1 + 1, v1.y);
        atomicAdd(dst1 + 2, v1.z);
        atomicAdd(dst1 + 3, v1.w);
    }
}

// ------------------------------------------------------------------
extern "C" void kernel_launch(void* const* d_in, const int* in_sizes, int n_in,
                              void* d_out, int out_size) {
    const int4*   coords = (const int4*)d_in[0];     // [N,4] int32
    const float4* feats  = (const float4*)d_in[1];   // [N,32] f32 as [N,8] float4
    float*        out    = (float*)d_out;            // [N,32] f32

    (void)in_sizes; (void)n_in; (void)out_size;

    const int TB = 256;

    // K1: reset bitmaps + lookback descriptors
    k_zero_bits<<<NWORDS / 4 / TB, TB>>>();
    // K2: keys + presence + dup detection (2 points/thread)
    k_mark<<<(NPTS / 2 + TB - 1) / TB, TB>>>(coords);
    // K3: fused single-pass scan + packed meta + dup-row zero + U
    k_scan_fused<<<SCAN_NBLK, SCAN_TPB>>>((float4*)d_out);
    // K4: scatter + tail zero (full-line store layout, packed meta)
    k_scatter<<<(NPTS * 4) / TB, TB>>>(feats, out);
}